// round 8
// baseline (speedup 1.0000x reference)
#include <cuda_runtime.h>
#include <cuda_bf16.h>
#include <cstdint>

#define NB    16
#define CIN   256
#define COUT  128
#define VRAW  10242
#define NVERT 40962
#define NPAIR (VRAW * 7)                  // 71694

#define BM    128
#define BNV   128
#define BK    32
#define NKCH  (CIN / BK)                  // 8
#define NVB   ((VRAW + BNV - 1) / BNV)    // 81

// Scratch (static __device__ — no allocation in kernel_launch)
__device__ float g_h[(size_t)NB * COUT * VRAW];   // 83.9 MB
__device__ __nv_bfloat16 g_Wh[COUT * CIN];
__device__ __nv_bfloat16 g_Wl[COUT * CIN];
__device__ int g_cnt[NVERT];                      // CSR counts / cursors
__device__ int g_off[NVERT + 1];                  // CSR offsets
__device__ int g_ent[NPAIR];                      // CSR entries: v*8+k

// ---------------- gemm smem layout (bytes) ----------------
#define A_STRIDE 80
#define B_STRIDE 272
#define F_STRIDE 528
#define A_TILE   (BM * A_STRIDE)
#define B_TILE   (BK * B_STRIDE)
#define F_TILE   (BK * F_STRIDE)
#define OFF_A    0
#define OFF_B    (4 * A_TILE)
#define OFF_F    (OFF_B + 4 * B_TILE)
#define SMEM_TOTAL (OFF_F + 2 * F_TILE)   // 109568

// ---------------- scatter smem layout ----------------
#define SC_MPI_BYTES (VRAW * 4 + 8)            // 40976 (8B aligned)
#define SC_SMEM      (SC_MPI_BYTES + VRAW * 4) // 81944 -> 2 CTAs/SM

// ---------------------------------------------------------------------------
__device__ __forceinline__ uint32_t smem_u32(const void* p) {
    uint32_t a;
    asm("{ .reg .u64 t; cvta.to.shared.u64 t, %1; cvt.u32.u64 %0, t; }"
        : "=r"(a) : "l"(p));
    return a;
}
__device__ __forceinline__ void cpa16(uint32_t dst, const void* src) {
    asm volatile("cp.async.cg.shared.global [%0], [%1], 16;"
                 :: "r"(dst), "l"(src) : "memory");
}
__device__ __forceinline__ void cpa8(uint32_t dst, const void* src) {
    asm volatile("cp.async.ca.shared.global [%0], [%1], 8;"
                 :: "r"(dst), "l"(src) : "memory");
}
__device__ __forceinline__ void cpa8z(uint32_t dst, const void* src, uint32_t bytes) {
    asm volatile("cp.async.ca.shared.global [%0], [%1], 8, %2;"
                 :: "r"(dst), "l"(src), "r"(bytes) : "memory");
}
#define CP_COMMIT() asm volatile("cp.async.commit_group;" ::: "memory")
#define CP_WAIT(N)  asm volatile("cp.async.wait_group %0;" :: "n"(N) : "memory")

__device__ __forceinline__ void ldsm4(uint32_t* r, uint32_t addr) {
    asm volatile("ldmatrix.sync.aligned.m8n8.x4.shared.b16 {%0,%1,%2,%3}, [%4];"
                 : "=r"(r[0]), "=r"(r[1]), "=r"(r[2]), "=r"(r[3]) : "r"(addr));
}
__device__ __forceinline__ void ldsm4t(uint32_t* r, uint32_t addr) {
    asm volatile("ldmatrix.sync.aligned.m8n8.x4.trans.shared.b16 {%0,%1,%2,%3}, [%4];"
                 : "=r"(r[0]), "=r"(r[1]), "=r"(r[2]), "=r"(r[3]) : "r"(addr));
}
__device__ __forceinline__ void mma_bf16(float* c, const uint32_t* a,
                                         uint32_t b0, uint32_t b1) {
    asm volatile(
        "mma.sync.aligned.m16n8k16.row.col.f32.bf16.bf16.f32 "
        "{%0,%1,%2,%3}, {%4,%5,%6,%7}, {%8,%9}, {%0,%1,%2,%3};"
        : "+f"(c[0]), "+f"(c[1]), "+f"(c[2]), "+f"(c[3])
        : "r"(a[0]), "r"(a[1]), "r"(a[2]), "r"(a[3]), "r"(b0), "r"(b1));
}

// ---- cheap two-term split
__device__ __forceinline__ uint32_t pack_hi(float a, float b) {
    uint32_t r;
    asm("prmt.b32 %0, %1, %2, 0x7632;"
        : "=r"(r) : "r"(__float_as_uint(a)), "r"(__float_as_uint(b)));
    return r;
}
__device__ __forceinline__ float hi_f(float a) {
    return __uint_as_float(__float_as_uint(a) & 0xFFFF0000u);
}
__device__ __forceinline__ uint32_t pack_lo(float a, float b) {
    float la = a - hi_f(a), lb = b - hi_f(b);
    uint32_t r;
    asm("cvt.rn.bf16x2.f32 %0, %1, %2;" : "=r"(r) : "f"(lb), "f"(la));
    return r;
}

// ---------------------------------------------------------------------------
// Kernel 0: split W -> g_Wh/g_Wl
// ---------------------------------------------------------------------------
__global__ __launch_bounds__(256) void convert_w_kernel(const float* __restrict__ W)
{
    int t = blockIdx.x * 256 + threadIdx.x;
    if (t >= COUT * CIN / 8) return;
    const float4* src = (const float4*)W + t * 2;
    float4 f0 = src[0], f1 = src[1];
    uint4 hi, lo;
    hi.x = pack_hi(f0.x, f0.y); lo.x = pack_lo(f0.x, f0.y);
    hi.y = pack_hi(f0.z, f0.w); lo.y = pack_lo(f0.z, f0.w);
    hi.z = pack_hi(f1.x, f1.y); lo.z = pack_lo(f1.x, f1.y);
    hi.w = pack_hi(f1.z, f1.w); lo.w = pack_lo(f1.z, f1.w);
    *(uint4*)(g_Wh + t * 8) = hi;
    *(uint4*)(g_Wl + t * 8) = lo;
}

// ---------------------------------------------------------------------------
// CSR inverse-map construction: vert = up[down[v]][k]  <-  (v,k)
// ---------------------------------------------------------------------------
__global__ void csr_zero_kernel()
{
    int i = blockIdx.x * blockDim.x + threadIdx.x;
    if (i < NVERT) g_cnt[i] = 0;
}
__global__ void csr_count_kernel(const int* __restrict__ up,
                                 const int* __restrict__ down)
{
    int i = blockIdx.x * blockDim.x + threadIdx.x;
    if (i >= NPAIR) return;
    int v = i / 7, k = i - v * 7;
    int vert = up[down[v] * 7 + k];
    atomicAdd(&g_cnt[vert], 1);
}
__global__ __launch_bounds__(1024) void csr_scan_kernel()
{
    __shared__ int part[1024];
    const int CH = (NVERT + 1023) / 1024;   // 41
    int t = threadIdx.x;
    int base = t * CH;
    int s = 0;
    for (int i = 0; i < CH; i++) {
        int j = base + i;
        if (j < NVERT) s += g_cnt[j];
    }
    part[t] = s;
    __syncthreads();
    for (int d = 1; d < 1024; d <<= 1) {
        int v = (t >= d) ? part[t - d] : 0;
        __syncthreads();
        part[t] += v;
        __syncthreads();
    }
    int run = (t > 0) ? part[t - 1] : 0;
    for (int i = 0; i < CH; i++) {
        int j = base + i;
        if (j < NVERT) {
            g_off[j] = run;
            run += g_cnt[j];
            g_cnt[j] = g_off[j];     // reuse as fill cursor
        }
    }
    if (t == 1023) g_off[NVERT] = part[1023];
}
__global__ void csr_fill_kernel(const int* __restrict__ up,
                                const int* __restrict__ down)
{
    int i = blockIdx.x * blockDim.x + threadIdx.x;
    if (i >= NPAIR) return;
    int v = i / 7, k = i - v * 7;
    int vert = up[down[v] * 7 + k];
    int pos = atomicAdd(&g_cnt[vert], 1);
    g_ent[pos] = (v << 3) | k;
}

// ---------------------------------------------------------------------------
// Kernel 2: HMMA GEMM (unchanged from R7).
// ---------------------------------------------------------------------------
__global__ __launch_bounds__(256, 2)
void gemm_mma_kernel(const float* __restrict__ x, const float* __restrict__ bias)
{
    extern __shared__ char smem[];
    const uint32_t sbase = smem_u32(smem);
    const int tid  = threadIdx.x;
    const int lane = tid & 31;
    const int wid  = tid >> 5;
    const int b    = blockIdx.y;
    const int v0   = blockIdx.x * BNV;
    const int wo   = (wid >> 2) * 64;
    const int wv   = (wid & 3) * 32;
    const bool fullv = (v0 + BNV) <= VRAW;

    float acc[4][4][4];
    #pragma unroll
    for (int i = 0; i < 4; i++)
        #pragma unroll
        for (int j = 0; j < 4; j++)
            #pragma unroll
            for (int e = 0; e < 4; e++) acc[i][j][e] = 0.f;

    auto issueA = [&](int kc, int buf) {
        int o = tid >> 1, half = tid & 1;
        const __nv_bfloat16* sh = g_Wh + o * CIN + kc + half * 16;
        const __nv_bfloat16* sl = g_Wl + o * CIN + kc + half * 16;
        uint32_t dh = sbase + OFF_A + (buf * 2 + 0) * A_TILE + o * A_STRIDE + half * 32;
        uint32_t dl = dh + A_TILE;
        cpa16(dh, sh); cpa16(dh + 16, sh + 8);
        cpa16(dl, sl); cpa16(dl + 16, sl + 8);
    };
    auto issueF = [&](int kc, int fb) {
        int c = tid >> 3, seg = tid & 7;
        const float* src = x + ((size_t)(b * CIN + kc + c)) * VRAW + v0 + seg * 16;
        uint32_t dst = sbase + OFF_F + fb * F_TILE + c * F_STRIDE + seg * 64;
        if (fullv) {
            #pragma unroll
            for (int j = 0; j < 8; j++) cpa8(dst + j * 8, src + j * 2);
        } else {
            #pragma unroll
            for (int j = 0; j < 8; j++) {
                int gv = v0 + seg * 16 + j * 2;
                uint32_t bytes = (gv + 2 <= VRAW) ? 8u : 0u;
                cpa8z(dst + j * 8, bytes ? (src + j * 2) : x, bytes);
            }
        }
    };
    auto convertB = [&](int buf) {
        int c = tid >> 3, seg = tid & 7;
        const char* fp = smem + OFF_F + (buf & 1) * F_TILE + c * F_STRIDE + seg * 64;
        float4 q0 = *(const float4*)(fp);
        float4 q1 = *(const float4*)(fp + 16);
        float4 q2 = *(const float4*)(fp + 32);
        float4 q3 = *(const float4*)(fp + 48);
        uint4 hi0, lo0, hi1, lo1;
        hi0.x = pack_hi(q0.x, q0.y); lo0.x = pack_lo(q0.x, q0.y);
        hi0.y = pack_hi(q0.z, q0.w); lo0.y = pack_lo(q0.z, q0.w);
        hi0.z = pack_hi(q1.x, q1.y); lo0.z = pack_lo(q1.x, q1.y);
        hi0.w = pack_hi(q1.z, q1.w); lo0.w = pack_lo(q1.z, q1.w);
        hi1.x = pack_hi(q2.x, q2.y); lo1.x = pack_lo(q2.x, q2.y);
        hi1.y = pack_hi(q2.z, q2.w); lo1.y = pack_lo(q2.z, q2.w);
        hi1.z = pack_hi(q3.x, q3.y); lo1.z = pack_lo(q3.x, q3.y);
        hi1.w = pack_hi(q3.z, q3.w); lo1.w = pack_lo(q3.z, q3.w);
        char* bh = smem + OFF_B + (buf * 2 + 0) * B_TILE + c * B_STRIDE + seg * 32;
        char* bl = bh + B_TILE;
        *(uint4*)(bh)      = hi0;  *(uint4*)(bh + 16) = hi1;
        *(uint4*)(bl)      = lo0;  *(uint4*)(bl + 16) = lo1;
    };

    const int arow   = lane & 15;
    const int acol16 = (lane >> 4) * 16;
    const int brow   = ((lane >> 3) & 1) * 8 + (lane & 7);
    const int bcol16 = (lane >> 4) * 16;

    auto compute = [&](int buf) {
        uint32_t ah4 = sbase + OFF_A + (buf * 2) * A_TILE + (wo + arow) * A_STRIDE + acol16;
        uint32_t al4 = ah4 + A_TILE;
        uint32_t bh4 = sbase + OFF_B + (buf * 2) * B_TILE + brow * B_STRIDE + wv * 2 + bcol16;
        uint32_t bl4 = bh4 + B_TILE;
        #pragma unroll
        for (int ks = 0; ks < 2; ks++) {
            uint32_t a_h[4][4], a_l[4][4], b_h[2][4], b_l[2][4];
            #pragma unroll
            for (int mi = 0; mi < 4; mi++)
                ldsm4(a_h[mi], ah4 + mi * 16 * A_STRIDE + ks * 32);
            #pragma unroll
            for (int np = 0; np < 2; np++)
                ldsm4t(b_h[np], bh4 + ks * 16 * B_STRIDE + np * 32);
            #pragma unroll
            for (int np = 0; np < 2; np++)
                ldsm4t(b_l[np], bl4 + ks * 16 * B_STRIDE + np * 32);
            #pragma unroll
            for (int mi = 0; mi < 4; mi++)
                ldsm4(a_l[mi], al4 + mi * 16 * A_STRIDE + ks * 32);
            #pragma unroll
            for (int mi = 0; mi < 4; mi++)
                #pragma unroll
                for (int nj = 0; nj < 4; nj++)
                    mma_bf16(acc[mi][nj], a_h[mi],
                             b_h[nj >> 1][(nj & 1) * 2], b_h[nj >> 1][(nj & 1) * 2 + 1]);
            #pragma unroll
            for (int mi = 0; mi < 4; mi++)
                #pragma unroll
                for (int nj = 0; nj < 4; nj++)
                    mma_bf16(acc[mi][nj], a_h[mi],
                             b_l[nj >> 1][(nj & 1) * 2], b_l[nj >> 1][(nj & 1) * 2 + 1]);
            #pragma unroll
            for (int mi = 0; mi < 4; mi++)
                #pragma unroll
                for (int nj = 0; nj < 4; nj++)
                    mma_bf16(acc[mi][nj], a_l[mi],
                             b_h[nj >> 1][(nj & 1) * 2], b_h[nj >> 1][(nj & 1) * 2 + 1]);
        }
    };

    issueF(0, 0); issueA(0, 0); CP_COMMIT();
    for (int kt = 0; kt < NKCH; kt++) {
        int buf = kt & 1;
        if (kt + 1 < NKCH) {
            issueF((kt + 1) * BK, buf ^ 1);
            issueA((kt + 1) * BK, buf ^ 1);
            CP_COMMIT();
            CP_WAIT(1);
        } else {
            CP_WAIT(0);
        }
        convertB(buf);
        __syncthreads();
        compute(buf);
        __syncthreads();
    }

    #pragma unroll
    for (int mi = 0; mi < 4; mi++) {
        int o0 = wo + mi * 16 + (lane >> 2);
        float b0 = __ldg(&bias[o0]);
        float b1 = __ldg(&bias[o0 + 8]);
        float* h0 = g_h + ((size_t)b * COUT + o0) * VRAW;
        float* h1 = h0 + (size_t)8 * VRAW;
        #pragma unroll
        for (int nj = 0; nj < 4; nj++) {
            int gv = v0 + wv + nj * 8 + (lane & 3) * 2;
            if (gv < VRAW) {
                *(float2*)(h0 + gv) = make_float2(acc[mi][nj][0] + b0,
                                                  acc[mi][nj][1] + b0);
                *(float2*)(h1 + gv) = make_float2(acc[mi][nj][2] + b1,
                                                  acc[mi][nj][3] + b1);
            }
        }
    }
}

// ---------------------------------------------------------------------------
// Kernel 3: gather-form scatter (no atomics, no win array).
// y[row][j] = h[row][v*], v* = max{v : (v,k) in inv[j], mpi[row][v]==k}
// ---------------------------------------------------------------------------
__global__ __launch_bounds__(1024, 2) void scatter_kernel(
    const int* __restrict__ mpi, float* __restrict__ y)
{
    extern __shared__ char sm[];
    int*   mpi_s = (int*)sm;                      // VRAW ints
    float* h_s   = (float*)(sm + SC_MPI_BYTES);   // VRAW floats
    const int row = blockIdx.x;
    const int tid = threadIdx.x;
    const uint32_t mpi_u = smem_u32(mpi_s);
    const uint32_t h_u   = smem_u32(h_s);

    // stage mpi row + h row via cp.async (both 8B-aligned, VRAW even)
    const int*   mrow = mpi + (size_t)row * VRAW;
    const float* hrow = g_h + (size_t)row * VRAW;
    for (int j = tid; j < VRAW / 2; j += 1024) {
        cpa8(mpi_u + j * 8, mrow + j * 2);
        cpa8(h_u + j * 8, hrow + j * 2);
    }
    CP_COMMIT();
    CP_WAIT(0);
    __syncthreads();

    // gather: two verts per iteration -> float2 stores
    float2* y2 = (float2*)(y + (size_t)row * NVERT);
    for (int idx = tid; idx < NVERT / 2; idx += 1024) {
        int j = idx * 2;
        int s0 = __ldg(&g_off[j]);
        int s1 = __ldg(&g_off[j + 1]);
        int s2 = __ldg(&g_off[j + 2]);
        int best0 = -1, best1 = -1;
        for (int t = s0; t < s1; t++) {
            int ent = __ldg(&g_ent[t]);
            int v = ent >> 3;
            if (mpi_s[v] == (ent & 7) && v > best0) best0 = v;
        }
        for (int t = s1; t < s2; t++) {
            int ent = __ldg(&g_ent[t]);
            int v = ent >> 3;
            if (mpi_s[v] == (ent & 7) && v > best1) best1 = v;
        }
        float2 o;
        o.x = (best0 >= 0) ? h_s[best0] : 0.f;
        o.y = (best1 >= 0) ? h_s[best1] : 0.f;
        y2[idx] = o;
    }
}

// ---------------------------------------------------------------------------
extern "C" void kernel_launch(void* const* d_in, const int* in_sizes, int n_in,
                              void* d_out, int out_size)
{
    const float* x    = (const float*)d_in[0];
    const float* W    = (const float*)d_in[1];
    const float* bias = (const float*)d_in[2];
    const int*   up   = (const int*)d_in[3];
    const int*   down = (const int*)d_in[4];
    const int*   mpi  = (const int*)d_in[5];
    float* y = (float*)d_out;

    cudaFuncSetAttribute(scatter_kernel,
                         cudaFuncAttributeMaxDynamicSharedMemorySize, SC_SMEM);
    cudaFuncSetAttribute(gemm_mma_kernel,
                         cudaFuncAttributeMaxDynamicSharedMemorySize, SMEM_TOTAL);

    convert_w_kernel<<<(COUT * CIN / 8 + 255) / 256, 256>>>(W);
    csr_zero_kernel<<<(NVERT + 255) / 256, 256>>>();
    csr_count_kernel<<<(NPAIR + 255) / 256, 256>>>(up, down);
    csr_scan_kernel<<<1, 1024>>>();
    csr_fill_kernel<<<(NPAIR + 255) / 256, 256>>>(up, down);

    dim3 g(NVB, NB);   // 81 x 16
    gemm_mma_kernel<<<g, 256, SMEM_TOTAL>>>(x, bias);

    scatter_kernel<<<NB * COUT, 1024, SC_SMEM>>>(mpi, y);
}

// round 9
// speedup vs baseline: 2.0147x; 2.0147x over previous
#include <cuda_runtime.h>
#include <cuda_bf16.h>
#include <cstdint>

#define NB    16
#define CIN   256
#define COUT  128
#define VRAW  10242
#define NVERT 40962
#define NROWS (NB * COUT)                 // 2048

#define BM    128
#define BNV   128
#define BK    32
#define NKCH  (CIN / BK)                  // 8
#define NVB   ((VRAW + BNV - 1) / BNV)    // 81

#define SC_GRID 148                       // persistent scatter CTAs (1/SM)

// Scratch (static __device__ — no allocation in kernel_launch)
__device__ float g_h[(size_t)NB * COUT * VRAW];   // 83.9 MB
__device__ int   g_nd[VRAW * 8];                  // 328 KB
__device__ __nv_bfloat16 g_Wh[COUT * CIN];
__device__ __nv_bfloat16 g_Wl[COUT * CIN];

// ---------------- gemm smem layout (bytes) ----------------
#define A_STRIDE 80
#define B_STRIDE 272
#define F_STRIDE 528
#define A_TILE   (BM * A_STRIDE)
#define B_TILE   (BK * B_STRIDE)
#define F_TILE   (BK * F_STRIDE)
#define OFF_A    0
#define OFF_B    (4 * A_TILE)
#define OFF_F    (OFF_B + 4 * B_TILE)
#define SMEM_TOTAL (OFF_F + 2 * F_TILE)   // 109568 (2 CTAs/SM)

// ---------------- scatter smem: win[] only ----------------
#define SC_SMEM (NVERT * 4 + 8)           // 163856

// ---------------------------------------------------------------------------
__device__ __forceinline__ uint32_t smem_u32(const void* p) {
    uint32_t a;
    asm("{ .reg .u64 t; cvta.to.shared.u64 t, %1; cvt.u32.u64 %0, t; }"
        : "=r"(a) : "l"(p));
    return a;
}
__device__ __forceinline__ void cpa16(uint32_t dst, const void* src) {
    asm volatile("cp.async.cg.shared.global [%0], [%1], 16;"
                 :: "r"(dst), "l"(src) : "memory");
}
__device__ __forceinline__ void cpa8(uint32_t dst, const void* src) {
    asm volatile("cp.async.ca.shared.global [%0], [%1], 8;"
                 :: "r"(dst), "l"(src) : "memory");
}
__device__ __forceinline__ void cpa8z(uint32_t dst, const void* src, uint32_t bytes) {
    asm volatile("cp.async.ca.shared.global [%0], [%1], 8, %2;"
                 :: "r"(dst), "l"(src), "r"(bytes) : "memory");
}
#define CP_COMMIT() asm volatile("cp.async.commit_group;" ::: "memory")
#define CP_WAIT(N)  asm volatile("cp.async.wait_group %0;" :: "n"(N) : "memory")

__device__ __forceinline__ void ldsm4(uint32_t* r, uint32_t addr) {
    asm volatile("ldmatrix.sync.aligned.m8n8.x4.shared.b16 {%0,%1,%2,%3}, [%4];"
                 : "=r"(r[0]), "=r"(r[1]), "=r"(r[2]), "=r"(r[3]) : "r"(addr));
}
__device__ __forceinline__ void ldsm4t(uint32_t* r, uint32_t addr) {
    asm volatile("ldmatrix.sync.aligned.m8n8.x4.trans.shared.b16 {%0,%1,%2,%3}, [%4];"
                 : "=r"(r[0]), "=r"(r[1]), "=r"(r[2]), "=r"(r[3]) : "r"(addr));
}
__device__ __forceinline__ void mma_bf16(float* c, const uint32_t* a,
                                         uint32_t b0, uint32_t b1) {
    asm volatile(
        "mma.sync.aligned.m16n8k16.row.col.f32.bf16.bf16.f32 "
        "{%0,%1,%2,%3}, {%4,%5,%6,%7}, {%8,%9}, {%0,%1,%2,%3};"
        : "+f"(c[0]), "+f"(c[1]), "+f"(c[2]), "+f"(c[3])
        : "r"(a[0]), "r"(a[1]), "r"(a[2]), "r"(a[3]), "r"(b0), "r"(b1));
}

// ---- cheap two-term split
__device__ __forceinline__ uint32_t pack_hi(float a, float b) {
    uint32_t r;
    asm("prmt.b32 %0, %1, %2, 0x7632;"
        : "=r"(r) : "r"(__float_as_uint(a)), "r"(__float_as_uint(b)));
    return r;
}
__device__ __forceinline__ float hi_f(float a) {
    return __uint_as_float(__float_as_uint(a) & 0xFFFF0000u);
}
__device__ __forceinline__ uint32_t pack_lo(float a, float b) {
    float la = a - hi_f(a), lb = b - hi_f(b);
    uint32_t r;
    asm("cvt.rn.bf16x2.f32 %0, %1, %2;" : "=r"(r) : "f"(lb), "f"(la));
    return r;
}

// ---------------------------------------------------------------------------
// Kernel 0: split W -> g_Wh/g_Wl
// ---------------------------------------------------------------------------
__global__ __launch_bounds__(256) void convert_w_kernel(const float* __restrict__ W)
{
    int t = blockIdx.x * 256 + threadIdx.x;
    if (t >= COUT * CIN / 8) return;
    const float4* src = (const float4*)W + t * 2;
    float4 f0 = src[0], f1 = src[1];
    uint4 hi, lo;
    hi.x = pack_hi(f0.x, f0.y); lo.x = pack_lo(f0.x, f0.y);
    hi.y = pack_hi(f0.z, f0.w); lo.y = pack_lo(f0.z, f0.w);
    hi.z = pack_hi(f1.x, f1.y); lo.z = pack_lo(f1.x, f1.y);
    hi.w = pack_hi(f1.z, f1.w); lo.w = pack_lo(f1.z, f1.w);
    *(uint4*)(g_Wh + t * 8) = hi;
    *(uint4*)(g_Wl + t * 8) = lo;
}

// ---------------------------------------------------------------------------
// Kernel 1: fold up_neigh[down[v]][k] into an int32 table
// ---------------------------------------------------------------------------
__global__ void prep_nd_kernel(const int* __restrict__ up,
                               const int* __restrict__ down)
{
    int i = blockIdx.x * blockDim.x + threadIdx.x;
    if (i >= VRAW * 8) return;
    int v = i >> 3, k = i & 7;
    int val = 0;
    if (k < 7) val = up[down[v] * 7 + k];
    g_nd[i] = val;
}

// ---------------------------------------------------------------------------
// Kernel 2: HMMA GEMM (identical to R7 — both syncs are load-bearing).
// ---------------------------------------------------------------------------
__global__ __launch_bounds__(256, 2)
void gemm_mma_kernel(const float* __restrict__ x, const float* __restrict__ bias)
{
    extern __shared__ char smem[];
    const uint32_t sbase = smem_u32(smem);
    const int tid  = threadIdx.x;
    const int lane = tid & 31;
    const int wid  = tid >> 5;
    const int b    = blockIdx.y;
    const int v0   = blockIdx.x * BNV;
    const int wo   = (wid >> 2) * 64;
    const int wv   = (wid & 3) * 32;
    const bool fullv = (v0 + BNV) <= VRAW;

    float acc[4][4][4];
    #pragma unroll
    for (int i = 0; i < 4; i++)
        #pragma unroll
        for (int j = 0; j < 4; j++)
            #pragma unroll
            for (int e = 0; e < 4; e++) acc[i][j][e] = 0.f;

    auto issueA = [&](int kc, int buf) {
        int o = tid >> 1, half = tid & 1;
        const __nv_bfloat16* sh = g_Wh + o * CIN + kc + half * 16;
        const __nv_bfloat16* sl = g_Wl + o * CIN + kc + half * 16;
        uint32_t dh = sbase + OFF_A + (buf * 2 + 0) * A_TILE + o * A_STRIDE + half * 32;
        uint32_t dl = dh + A_TILE;
        cpa16(dh, sh); cpa16(dh + 16, sh + 8);
        cpa16(dl, sl); cpa16(dl + 16, sl + 8);
    };
    auto issueF = [&](int kc, int fb) {
        int c = tid >> 3, seg = tid & 7;
        const float* src = x + ((size_t)(b * CIN + kc + c)) * VRAW + v0 + seg * 16;
        uint32_t dst = sbase + OFF_F + fb * F_TILE + c * F_STRIDE + seg * 64;
        if (fullv) {
            #pragma unroll
            for (int j = 0; j < 8; j++) cpa8(dst + j * 8, src + j * 2);
        } else {
            #pragma unroll
            for (int j = 0; j < 8; j++) {
                int gv = v0 + seg * 16 + j * 2;
                uint32_t bytes = (gv + 2 <= VRAW) ? 8u : 0u;
                cpa8z(dst + j * 8, bytes ? (src + j * 2) : x, bytes);
            }
        }
    };
    auto convertB = [&](int buf) {
        int c = tid >> 3, seg = tid & 7;
        const char* fp = smem + OFF_F + (buf & 1) * F_TILE + c * F_STRIDE + seg * 64;
        float4 q0 = *(const float4*)(fp);
        float4 q1 = *(const float4*)(fp + 16);
        float4 q2 = *(const float4*)(fp + 32);
        float4 q3 = *(const float4*)(fp + 48);
        uint4 hi0, lo0, hi1, lo1;
        hi0.x = pack_hi(q0.x, q0.y); lo0.x = pack_lo(q0.x, q0.y);
        hi0.y = pack_hi(q0.z, q0.w); lo0.y = pack_lo(q0.z, q0.w);
        hi0.z = pack_hi(q1.x, q1.y); lo0.z = pack_lo(q1.x, q1.y);
        hi0.w = pack_hi(q1.z, q1.w); lo0.w = pack_lo(q1.z, q1.w);
        hi1.x = pack_hi(q2.x, q2.y); lo1.x = pack_lo(q2.x, q2.y);
        hi1.y = pack_hi(q2.z, q2.w); lo1.y = pack_lo(q2.z, q2.w);
        hi1.z = pack_hi(q3.x, q3.y); lo1.z = pack_lo(q3.x, q3.y);
        hi1.w = pack_hi(q3.z, q3.w); lo1.w = pack_lo(q3.z, q3.w);
        char* bh = smem + OFF_B + (buf * 2 + 0) * B_TILE + c * B_STRIDE + seg * 32;
        char* bl = bh + B_TILE;
        *(uint4*)(bh)      = hi0;  *(uint4*)(bh + 16) = hi1;
        *(uint4*)(bl)      = lo0;  *(uint4*)(bl + 16) = lo1;
    };

    const int arow   = lane & 15;
    const int acol16 = (lane >> 4) * 16;
    const int brow   = ((lane >> 3) & 1) * 8 + (lane & 7);
    const int bcol16 = (lane >> 4) * 16;

    auto compute = [&](int buf) {
        uint32_t ah4 = sbase + OFF_A + (buf * 2) * A_TILE + (wo + arow) * A_STRIDE + acol16;
        uint32_t al4 = ah4 + A_TILE;
        uint32_t bh4 = sbase + OFF_B + (buf * 2) * B_TILE + brow * B_STRIDE + wv * 2 + bcol16;
        uint32_t bl4 = bh4 + B_TILE;
        #pragma unroll
        for (int ks = 0; ks < 2; ks++) {
            uint32_t a_h[4][4], a_l[4][4], b_h[2][4], b_l[2][4];
            #pragma unroll
            for (int mi = 0; mi < 4; mi++)
                ldsm4(a_h[mi], ah4 + mi * 16 * A_STRIDE + ks * 32);
            #pragma unroll
            for (int np = 0; np < 2; np++)
                ldsm4t(b_h[np], bh4 + ks * 16 * B_STRIDE + np * 32);
            #pragma unroll
            for (int np = 0; np < 2; np++)
                ldsm4t(b_l[np], bl4 + ks * 16 * B_STRIDE + np * 32);
            #pragma unroll
            for (int mi = 0; mi < 4; mi++)
                ldsm4(a_l[mi], al4 + mi * 16 * A_STRIDE + ks * 32);
            #pragma unroll
            for (int mi = 0; mi < 4; mi++)
                #pragma unroll
                for (int nj = 0; nj < 4; nj++)
                    mma_bf16(acc[mi][nj], a_h[mi],
                             b_h[nj >> 1][(nj & 1) * 2], b_h[nj >> 1][(nj & 1) * 2 + 1]);
            #pragma unroll
            for (int mi = 0; mi < 4; mi++)
                #pragma unroll
                for (int nj = 0; nj < 4; nj++)
                    mma_bf16(acc[mi][nj], a_h[mi],
                             b_l[nj >> 1][(nj & 1) * 2], b_l[nj >> 1][(nj & 1) * 2 + 1]);
            #pragma unroll
            for (int mi = 0; mi < 4; mi++)
                #pragma unroll
                for (int nj = 0; nj < 4; nj++)
                    mma_bf16(acc[mi][nj], a_l[mi],
                             b_h[nj >> 1][(nj & 1) * 2], b_h[nj >> 1][(nj & 1) * 2 + 1]);
        }
    };

    issueF(0, 0); issueA(0, 0); CP_COMMIT();
    for (int kt = 0; kt < NKCH; kt++) {
        int buf = kt & 1;
        if (kt + 1 < NKCH) {
            issueF((kt + 1) * BK, buf ^ 1);
            issueA((kt + 1) * BK, buf ^ 1);
            CP_COMMIT();
            CP_WAIT(1);
        } else {
            CP_WAIT(0);
        }
        convertB(buf);
        __syncthreads();
        compute(buf);
        __syncthreads();
    }

    #pragma unroll
    for (int mi = 0; mi < 4; mi++) {
        int o0 = wo + mi * 16 + (lane >> 2);
        float b0 = __ldg(&bias[o0]);
        float b1 = __ldg(&bias[o0 + 8]);
        float* h0 = g_h + ((size_t)b * COUT + o0) * VRAW;
        float* h1 = h0 + (size_t)8 * VRAW;
        #pragma unroll
        for (int nj = 0; nj < 4; nj++) {
            int gv = v0 + wv + nj * 8 + (lane & 3) * 2;
            if (gv < VRAW) {
                *(float2*)(h0 + gv) = make_float2(acc[mi][nj][0] + b0,
                                                  acc[mi][nj][1] + b0);
                *(float2*)(h1 + gv) = make_float2(acc[mi][nj][2] + b1,
                                                  acc[mi][nj][3] + b1);
            }
        }
    }
}

// ---------------------------------------------------------------------------
// Kernel 3: persistent scatter, last-write-wins (max v).
// 148 CTAs loop over rows; win[] reset fused into the write phase; next row's
// mpi LDGs issued before the write phase; h gathered via __ldg (L1-resident).
// ---------------------------------------------------------------------------
__global__ __launch_bounds__(1024, 1) void scatter_kernel(
    const int* __restrict__ mpi, float* __restrict__ y)
{
    extern __shared__ int win[];      // NVERT ints
    const int tid = threadIdx.x;

    // one-time memset (vectorized): 40962 = 10240*4 + 2
    {
        int4* w4 = (int4*)win;
        int4 m1 = make_int4(-1, -1, -1, -1);
        #pragma unroll
        for (int i = 0; i < 10; i++) w4[tid + (i << 10)] = m1;
        if (tid < 2) win[40960 + tid] = -1;
    }

    int row = blockIdx.x;
    // prefetch first row's mpi into registers
    int mk[11];
    {
        const int* mrow = mpi + (size_t)row * VRAW;
        #pragma unroll
        for (int i = 0; i < 11; i++) {
            int v = tid + (i << 10);
            mk[i] = (v < VRAW) ? __ldg(&mrow[v]) : 0;
        }
    }
    __syncthreads();

    while (row < NROWS) {
        // atomics phase (mpi already in regs)
        #pragma unroll
        for (int i = 0; i < 11; i++) {
            int v = tid + (i << 10);
            if (v < VRAW) {
                int vert = g_nd[(v << 3) + mk[i]];
                atomicMax(&win[vert], v);
            }
        }

        // issue next row's mpi loads now; latency hides under the write phase
        int row2 = row + SC_GRID;
        int mk2[11];
        if (row2 < NROWS) {
            const int* mrow2 = mpi + (size_t)row2 * VRAW;
            #pragma unroll
            for (int i = 0; i < 11; i++) {
                int v = tid + (i << 10);
                mk2[i] = (v < VRAW) ? __ldg(&mrow2[v]) : 0;
            }
        }
        __syncthreads();   // all atomics done before win reads

        // write phase + fused reset (covers all NVERT entries: 20481 pairs)
        const float* hrow = g_h + (size_t)row * VRAW;
        float2* y2 = (float2*)(y + (size_t)row * NVERT);
        const int2 m2 = make_int2(-1, -1);
        for (int idx = tid; idx < NVERT / 2; idx += 1024) {
            int2 w = *(int2*)&win[idx * 2];
            *(int2*)&win[idx * 2] = m2;               // reset for next row
            float2 o;
            o.x = (w.x >= 0) ? __ldg(&hrow[w.x]) : 0.f;
            o.y = (w.y >= 0) ? __ldg(&hrow[w.y]) : 0.f;
            y2[idx] = o;
        }
        __syncthreads();   // resets visible before next row's atomics

        row = row2;
        #pragma unroll
        for (int i = 0; i < 11; i++) mk[i] = mk2[i];
    }
}

// ---------------------------------------------------------------------------
extern "C" void kernel_launch(void* const* d_in, const int* in_sizes, int n_in,
                              void* d_out, int out_size)
{
    const float* x    = (const float*)d_in[0];
    const float* W    = (const float*)d_in[1];
    const float* bias = (const float*)d_in[2];
    const int*   up   = (const int*)d_in[3];
    const int*   down = (const int*)d_in[4];
    const int*   mpi  = (const int*)d_in[5];
    float* y = (float*)d_out;

    cudaFuncSetAttribute(scatter_kernel,
                         cudaFuncAttributeMaxDynamicSharedMemorySize, SC_SMEM);
    cudaFuncSetAttribute(gemm_mma_kernel,
                         cudaFuncAttributeMaxDynamicSharedMemorySize, SMEM_TOTAL);

    convert_w_kernel<<<(COUT * CIN / 8 + 255) / 256, 256>>>(W);
    prep_nd_kernel<<<(VRAW * 8 + 255) / 256, 256>>>(up, down);

    dim3 g(NVB, NB);   // 81 x 16
    gemm_mma_kernel<<<g, 256, SMEM_TOTAL>>>(x, bias);

    scatter_kernel<<<SC_GRID, 1024, SC_SMEM>>>(mpi, y);
}

// round 10
// speedup vs baseline: 2.0359x; 1.0105x over previous
#include <cuda_runtime.h>
#include <cuda_bf16.h>
#include <cstdint>

#define NB    16
#define CIN   256
#define COUT  128
#define VRAW  10242
#define NVERT 40962
#define NROWS (NB * COUT)                 // 2048

#define BM    128
#define BNV   128
#define BK    32
#define NKCH  (CIN / BK)                  // 8
#define NVB   ((VRAW + BNV - 1) / BNV)    // 81

#define SC_GRID 148                       // persistent scatter CTAs (1/SM)

// Scratch (static __device__ — no allocation in kernel_launch)
__device__ float g_h[(size_t)NB * COUT * VRAW];   // 83.9 MB
__device__ int   g_nd[VRAW * 8];                  // 328 KB
__device__ __nv_bfloat16 g_Wh[COUT * CIN];
__device__ __nv_bfloat16 g_Wl[COUT * CIN];

// ---------------- gemm smem layout (bytes) ----------------
#define A_STRIDE 80
#define B_STRIDE 272
#define F_STRIDE 528
#define A_TILE   (BM * A_STRIDE)
#define B_TILE   (BK * B_STRIDE)
#define F_TILE   (BK * F_STRIDE)
#define OFF_A    0
#define OFF_B    (4 * A_TILE)
#define OFF_F    (OFF_B + 4 * B_TILE)
#define SMEM_TOTAL (OFF_F + 2 * F_TILE)   // 109568 (2 CTAs/SM)

// ---------------- scatter smem: win[] only ----------------
#define SC_SMEM (NVERT * 4 + 8)           // 163856

// ---------------------------------------------------------------------------
__device__ __forceinline__ uint32_t smem_u32(const void* p) {
    uint32_t a;
    asm("{ .reg .u64 t; cvta.to.shared.u64 t, %1; cvt.u32.u64 %0, t; }"
        : "=r"(a) : "l"(p));
    return a;
}
__device__ __forceinline__ void cpa16(uint32_t dst, const void* src) {
    asm volatile("cp.async.cg.shared.global [%0], [%1], 16;"
                 :: "r"(dst), "l"(src) : "memory");
}
__device__ __forceinline__ void cpa8(uint32_t dst, const void* src) {
    asm volatile("cp.async.ca.shared.global [%0], [%1], 8;"
                 :: "r"(dst), "l"(src) : "memory");
}
__device__ __forceinline__ void cpa8z(uint32_t dst, const void* src, uint32_t bytes) {
    asm volatile("cp.async.ca.shared.global [%0], [%1], 8, %2;"
                 :: "r"(dst), "l"(src), "r"(bytes) : "memory");
}
#define CP_COMMIT() asm volatile("cp.async.commit_group;" ::: "memory")
#define CP_WAIT(N)  asm volatile("cp.async.wait_group %0;" :: "n"(N) : "memory")

__device__ __forceinline__ void ldsm4(uint32_t* r, uint32_t addr) {
    asm volatile("ldmatrix.sync.aligned.m8n8.x4.shared.b16 {%0,%1,%2,%3}, [%4];"
                 : "=r"(r[0]), "=r"(r[1]), "=r"(r[2]), "=r"(r[3]) : "r"(addr));
}
__device__ __forceinline__ void ldsm4t(uint32_t* r, uint32_t addr) {
    asm volatile("ldmatrix.sync.aligned.m8n8.x4.trans.shared.b16 {%0,%1,%2,%3}, [%4];"
                 : "=r"(r[0]), "=r"(r[1]), "=r"(r[2]), "=r"(r[3]) : "r"(addr));
}
__device__ __forceinline__ void mma_bf16(float* c, const uint32_t* a,
                                         uint32_t b0, uint32_t b1) {
    asm volatile(
        "mma.sync.aligned.m16n8k16.row.col.f32.bf16.bf16.f32 "
        "{%0,%1,%2,%3}, {%4,%5,%6,%7}, {%8,%9}, {%0,%1,%2,%3};"
        : "+f"(c[0]), "+f"(c[1]), "+f"(c[2]), "+f"(c[3])
        : "r"(a[0]), "r"(a[1]), "r"(a[2]), "r"(a[3]), "r"(b0), "r"(b1));
}

// ---- cheap two-term split
__device__ __forceinline__ uint32_t pack_hi(float a, float b) {
    uint32_t r;
    asm("prmt.b32 %0, %1, %2, 0x7632;"
        : "=r"(r) : "r"(__float_as_uint(a)), "r"(__float_as_uint(b)));
    return r;
}
__device__ __forceinline__ float hi_f(float a) {
    return __uint_as_float(__float_as_uint(a) & 0xFFFF0000u);
}
__device__ __forceinline__ uint32_t pack_lo(float a, float b) {
    float la = a - hi_f(a), lb = b - hi_f(b);
    uint32_t r;
    asm("cvt.rn.bf16x2.f32 %0, %1, %2;" : "=r"(r) : "f"(lb), "f"(la));
    return r;
}

// ---------------------------------------------------------------------------
// Kernel 0: merged prep — blocks [0,16): split W; blocks [16,337): nd table
// ---------------------------------------------------------------------------
#define PREP_W_BLOCKS 16
__global__ __launch_bounds__(256) void prep_kernel(const float* __restrict__ W,
                                                   const int* __restrict__ up,
                                                   const int* __restrict__ down)
{
    if (blockIdx.x < PREP_W_BLOCKS) {
        int t = blockIdx.x * 256 + threadIdx.x;
        if (t >= COUT * CIN / 8) return;
        const float4* src = (const float4*)W + t * 2;
        float4 f0 = src[0], f1 = src[1];
        uint4 hi, lo;
        hi.x = pack_hi(f0.x, f0.y); lo.x = pack_lo(f0.x, f0.y);
        hi.y = pack_hi(f0.z, f0.w); lo.y = pack_lo(f0.z, f0.w);
        hi.z = pack_hi(f1.x, f1.y); lo.z = pack_lo(f1.x, f1.y);
        hi.w = pack_hi(f1.z, f1.w); lo.w = pack_lo(f1.z, f1.w);
        *(uint4*)(g_Wh + t * 8) = hi;
        *(uint4*)(g_Wl + t * 8) = lo;
    } else {
        int i = (blockIdx.x - PREP_W_BLOCKS) * 256 + threadIdx.x;
        if (i >= VRAW * 8) return;
        int v = i >> 3, k = i & 7;
        int val = 0;
        if (k < 7) val = up[down[v] * 7 + k];
        g_nd[i] = val;
    }
}

// ---------------------------------------------------------------------------
// Kernel 2: HMMA GEMM (identical to R9).
// ---------------------------------------------------------------------------
__global__ __launch_bounds__(256, 2)
void gemm_mma_kernel(const float* __restrict__ x, const float* __restrict__ bias)
{
    extern __shared__ char smem[];
    const uint32_t sbase = smem_u32(smem);
    const int tid  = threadIdx.x;
    const int lane = tid & 31;
    const int wid  = tid >> 5;
    const int b    = blockIdx.y;
    const int v0   = blockIdx.x * BNV;
    const int wo   = (wid >> 2) * 64;
    const int wv   = (wid & 3) * 32;
    const bool fullv = (v0 + BNV) <= VRAW;

    float acc[4][4][4];
    #pragma unroll
    for (int i = 0; i < 4; i++)
        #pragma unroll
        for (int j = 0; j < 4; j++)
            #pragma unroll
            for (int e = 0; e < 4; e++) acc[i][j][e] = 0.f;

    auto issueA = [&](int kc, int buf) {
        int o = tid >> 1, half = tid & 1;
        const __nv_bfloat16* sh = g_Wh + o * CIN + kc + half * 16;
        const __nv_bfloat16* sl = g_Wl + o * CIN + kc + half * 16;
        uint32_t dh = sbase + OFF_A + (buf * 2 + 0) * A_TILE + o * A_STRIDE + half * 32;
        uint32_t dl = dh + A_TILE;
        cpa16(dh, sh); cpa16(dh + 16, sh + 8);
        cpa16(dl, sl); cpa16(dl + 16, sl + 8);
    };
    auto issueF = [&](int kc, int fb) {
        int c = tid >> 3, seg = tid & 7;
        const float* src = x + ((size_t)(b * CIN + kc + c)) * VRAW + v0 + seg * 16;
        uint32_t dst = sbase + OFF_F + fb * F_TILE + c * F_STRIDE + seg * 64;
        if (fullv) {
            #pragma unroll
            for (int j = 0; j < 8; j++) cpa8(dst + j * 8, src + j * 2);
        } else {
            #pragma unroll
            for (int j = 0; j < 8; j++) {
                int gv = v0 + seg * 16 + j * 2;
                uint32_t bytes = (gv + 2 <= VRAW) ? 8u : 0u;
                cpa8z(dst + j * 8, bytes ? (src + j * 2) : x, bytes);
            }
        }
    };
    auto convertB = [&](int buf) {
        int c = tid >> 3, seg = tid & 7;
        const char* fp = smem + OFF_F + (buf & 1) * F_TILE + c * F_STRIDE + seg * 64;
        float4 q0 = *(const float4*)(fp);
        float4 q1 = *(const float4*)(fp + 16);
        float4 q2 = *(const float4*)(fp + 32);
        float4 q3 = *(const float4*)(fp + 48);
        uint4 hi0, lo0, hi1, lo1;
        hi0.x = pack_hi(q0.x, q0.y); lo0.x = pack_lo(q0.x, q0.y);
        hi0.y = pack_hi(q0.z, q0.w); lo0.y = pack_lo(q0.z, q0.w);
        hi0.z = pack_hi(q1.x, q1.y); lo0.z = pack_lo(q1.x, q1.y);
        hi0.w = pack_hi(q1.z, q1.w); lo0.w = pack_lo(q1.z, q1.w);
        hi1.x = pack_hi(q2.x, q2.y); lo1.x = pack_lo(q2.x, q2.y);
        hi1.y = pack_hi(q2.z, q2.w); lo1.y = pack_lo(q2.z, q2.w);
        hi1.z = pack_hi(q3.x, q3.y); lo1.z = pack_lo(q3.x, q3.y);
        hi1.w = pack_hi(q3.z, q3.w); lo1.w = pack_lo(q3.z, q3.w);
        char* bh = smem + OFF_B + (buf * 2 + 0) * B_TILE + c * B_STRIDE + seg * 32;
        char* bl = bh + B_TILE;
        *(uint4*)(bh)      = hi0;  *(uint4*)(bh + 16) = hi1;
        *(uint4*)(bl)      = lo0;  *(uint4*)(bl + 16) = lo1;
    };

    const int arow   = lane & 15;
    const int acol16 = (lane >> 4) * 16;
    const int brow   = ((lane >> 3) & 1) * 8 + (lane & 7);
    const int bcol16 = (lane >> 4) * 16;

    auto compute = [&](int buf) {
        uint32_t ah4 = sbase + OFF_A + (buf * 2) * A_TILE + (wo + arow) * A_STRIDE + acol16;
        uint32_t al4 = ah4 + A_TILE;
        uint32_t bh4 = sbase + OFF_B + (buf * 2) * B_TILE + brow * B_STRIDE + wv * 2 + bcol16;
        uint32_t bl4 = bh4 + B_TILE;
        #pragma unroll
        for (int ks = 0; ks < 2; ks++) {
            uint32_t a_h[4][4], a_l[4][4], b_h[2][4], b_l[2][4];
            #pragma unroll
            for (int mi = 0; mi < 4; mi++)
                ldsm4(a_h[mi], ah4 + mi * 16 * A_STRIDE + ks * 32);
            #pragma unroll
            for (int np = 0; np < 2; np++)
                ldsm4t(b_h[np], bh4 + ks * 16 * B_STRIDE + np * 32);
            #pragma unroll
            for (int np = 0; np < 2; np++)
                ldsm4t(b_l[np], bl4 + ks * 16 * B_STRIDE + np * 32);
            #pragma unroll
            for (int mi = 0; mi < 4; mi++)
                ldsm4(a_l[mi], al4 + mi * 16 * A_STRIDE + ks * 32);
            #pragma unroll
            for (int mi = 0; mi < 4; mi++)
                #pragma unroll
                for (int nj = 0; nj < 4; nj++)
                    mma_bf16(acc[mi][nj], a_h[mi],
                             b_h[nj >> 1][(nj & 1) * 2], b_h[nj >> 1][(nj & 1) * 2 + 1]);
            #pragma unroll
            for (int mi = 0; mi < 4; mi++)
                #pragma unroll
                for (int nj = 0; nj < 4; nj++)
                    mma_bf16(acc[mi][nj], a_h[mi],
                             b_l[nj >> 1][(nj & 1) * 2], b_l[nj >> 1][(nj & 1) * 2 + 1]);
            #pragma unroll
            for (int mi = 0; mi < 4; mi++)
                #pragma unroll
                for (int nj = 0; nj < 4; nj++)
                    mma_bf16(acc[mi][nj], a_l[mi],
                             b_h[nj >> 1][(nj & 1) * 2], b_h[nj >> 1][(nj & 1) * 2 + 1]);
        }
    };

    issueF(0, 0); issueA(0, 0); CP_COMMIT();
    for (int kt = 0; kt < NKCH; kt++) {
        int buf = kt & 1;
        if (kt + 1 < NKCH) {
            issueF((kt + 1) * BK, buf ^ 1);
            issueA((kt + 1) * BK, buf ^ 1);
            CP_COMMIT();
            CP_WAIT(1);
        } else {
            CP_WAIT(0);
        }
        convertB(buf);
        __syncthreads();
        compute(buf);
        __syncthreads();
    }

    #pragma unroll
    for (int mi = 0; mi < 4; mi++) {
        int o0 = wo + mi * 16 + (lane >> 2);
        float b0 = __ldg(&bias[o0]);
        float b1 = __ldg(&bias[o0 + 8]);
        float* h0 = g_h + ((size_t)b * COUT + o0) * VRAW;
        float* h1 = h0 + (size_t)8 * VRAW;
        #pragma unroll
        for (int nj = 0; nj < 4; nj++) {
            int gv = v0 + wv + nj * 8 + (lane & 3) * 2;
            if (gv < VRAW) {
                *(float2*)(h0 + gv) = make_float2(acc[mi][nj][0] + b0,
                                                  acc[mi][nj][1] + b0);
                *(float2*)(h1 + gv) = make_float2(acc[mi][nj][2] + b1,
                                                  acc[mi][nj][3] + b1);
            }
        }
    }
}

// ---------------------------------------------------------------------------
// Kernel 3: persistent scatter, epoch-encoded win (no reset pass),
// 4-wide write phase with aligned STG.128.
// win[vert] = (epoch << 14) | v ; valid iff (w>>14)==epoch ; max-v wins.
// ---------------------------------------------------------------------------
__global__ __launch_bounds__(1024, 1) void scatter_kernel(
    const int* __restrict__ mpi, float* __restrict__ y)
{
    extern __shared__ int win[];      // NVERT ints
    const int tid = threadIdx.x;

    // one-time zero (epoch starts at 1, so 0 never matches)
    {
        int4* w4 = (int4*)win;
        int4 z = make_int4(0, 0, 0, 0);
        #pragma unroll
        for (int i = 0; i < 10; i++) w4[tid + (i << 10)] = z;
        if (tid < 2) win[40960 + tid] = 0;
    }

    int row = blockIdx.x;
    int epoch = 1;
    // prefetch first row's mpi
    int mk[11];
    {
        const int* mrow = mpi + (size_t)row * VRAW;
        #pragma unroll
        for (int i = 0; i < 11; i++) {
            int v = tid + (i << 10);
            mk[i] = (v < VRAW) ? __ldg(&mrow[v]) : 0;
        }
    }
    __syncthreads();

    while (row < NROWS) {
        const int tag = epoch << 14;
        // atomics phase
        #pragma unroll
        for (int i = 0; i < 11; i++) {
            int v = tid + (i << 10);
            if (v < VRAW) {
                int vert = g_nd[(v << 3) + mk[i]];
                atomicMax(&win[vert], tag | v);
            }
        }

        // prefetch next row's mpi (hides under write phase)
        int row2 = row + SC_GRID;
        int mk2[11];
        if (row2 < NROWS) {
            const int* mrow2 = mpi + (size_t)row2 * VRAW;
            #pragma unroll
            for (int i = 0; i < 11; i++) {
                int v = tid + (i << 10);
                mk2[i] = (v < VRAW) ? __ldg(&mrow2[v]) : 0;
            }
        }
        __syncthreads();   // atomics done before win reads

        // write phase: 10240 aligned float4 quads + a pair at the ragged end.
        // y row base byte ≡ 8 (mod 16) for odd rows -> quads start at vert 2.
        const float* hrow = g_h + (size_t)row * VRAW;
        float* yrow = y + (size_t)row * NVERT;
        const int s0 = (row & 1) ? 2 : 0;
        if (tid == 0) {   // pre/tail pair (2 verts)
            int jp = (row & 1) ? 0 : 40960;
            int w0 = win[jp], w1 = win[jp + 1];
            float2 o;
            o.x = ((w0 >> 14) == epoch) ? __ldg(&hrow[w0 & 16383]) : 0.f;
            o.y = ((w1 >> 14) == epoch) ? __ldg(&hrow[w1 & 16383]) : 0.f;
            *(float2*)(yrow + jp) = o;
        }
        #pragma unroll
        for (int it = 0; it < 10; it++) {
            int q = tid + (it << 10);          // 0..10239
            int j = s0 + q * 4;
            int2 wa = *(const int2*)&win[j];
            int2 wb = *(const int2*)&win[j + 2];
            float4 o;
            o.x = ((wa.x >> 14) == epoch) ? __ldg(&hrow[wa.x & 16383]) : 0.f;
            o.y = ((wa.y >> 14) == epoch) ? __ldg(&hrow[wa.y & 16383]) : 0.f;
            o.z = ((wb.x >> 14) == epoch) ? __ldg(&hrow[wb.x & 16383]) : 0.f;
            o.w = ((wb.y >> 14) == epoch) ? __ldg(&hrow[wb.y & 16383]) : 0.f;
            *(float4*)(yrow + j) = o;
        }
        __syncthreads();   // win reads done before next row's atomics

        row = row2;
        epoch++;
        #pragma unroll
        for (int i = 0; i < 11; i++) mk[i] = mk2[i];
    }
}

// ---------------------------------------------------------------------------
extern "C" void kernel_launch(void* const* d_in, const int* in_sizes, int n_in,
                              void* d_out, int out_size)
{
    const float* x    = (const float*)d_in[0];
    const float* W    = (const float*)d_in[1];
    const float* bias = (const float*)d_in[2];
    const int*   up   = (const int*)d_in[3];
    const int*   down = (const int*)d_in[4];
    const int*   mpi  = (const int*)d_in[5];
    float* y = (float*)d_out;

    cudaFuncSetAttribute(scatter_kernel,
                         cudaFuncAttributeMaxDynamicSharedMemorySize, SC_SMEM);
    cudaFuncSetAttribute(gemm_mma_kernel,
                         cudaFuncAttributeMaxDynamicSharedMemorySize, SMEM_TOTAL);

    prep_kernel<<<PREP_W_BLOCKS + (VRAW * 8 + 255) / 256, 256>>>(W, up, down);

    dim3 g(NVB, NB);   // 81 x 16
    gemm_mma_kernel<<<g, 256, SMEM_TOTAL>>>(x, bias);

    scatter_kernel<<<SC_GRID, 1024, SC_SMEM>>>(mpi, y);
}